// round 1
// baseline (speedup 1.0000x reference)
#include <cuda_runtime.h>
#include <math.h>

#define B_  32
#define T_  512
#define H_  1024
#define G4  4096   // 4*H

// Persistent scratch (no cudaMalloc allowed)
__device__ float g_xz[B_ * T_ * G4];      // [B*T, 4H] input projection
__device__ float g_h[2][B_ * H_];         // double-buffered hidden state
__device__ float g_c[B_ * H_];            // cell state

// ---------------------------------------------------------------------------
// Kernel 0: zero h[0] and c  (re-run every replay for determinism)
// ---------------------------------------------------------------------------
__global__ void init_state() {
    int i = blockIdx.x * blockDim.x + threadIdx.x;
    if (i < B_ * H_) {
        g_h[0][i] = 0.0f;
        g_c[i]    = 0.0f;
    }
}

// ---------------------------------------------------------------------------
// Kernel 1: xz = x @ W + b     (M=16384, N=4096, K=1024, fp32)
// 128x128 tile, BK=8, 256 threads, 8x8 microtile
// ---------------------------------------------------------------------------
__global__ __launch_bounds__(256) void xw_gemm(const float* __restrict__ X,
                                               const float* __restrict__ W,
                                               const float* __restrict__ bias) {
    __shared__ float As[8][128];
    __shared__ float Bs[8][128];

    const int tid  = threadIdx.x;
    const int row0 = blockIdx.y * 128;
    const int col0 = blockIdx.x * 128;

    const int aRow = tid >> 1;           // 0..127
    const int aCol = (tid & 1) * 4;      // 0 or 4
    const int bRow = tid >> 5;           // 0..7
    const int bCol = (tid & 31) * 4;     // 0..124

    const int ty = (tid >> 4) * 8;       // 0..120
    const int tx = (tid & 15) * 8;       // 0..120

    float acc[8][8];
#pragma unroll
    for (int i = 0; i < 8; i++)
#pragma unroll
        for (int j = 0; j < 8; j++) acc[i][j] = 0.0f;

    for (int k0 = 0; k0 < H_; k0 += 8) {
        float4 a = *(const float4*)(X + (size_t)(row0 + aRow) * H_ + k0 + aCol);
        As[aCol + 0][aRow] = a.x;
        As[aCol + 1][aRow] = a.y;
        As[aCol + 2][aRow] = a.z;
        As[aCol + 3][aRow] = a.w;
        float4 bv = *(const float4*)(W + (size_t)(k0 + bRow) * G4 + col0 + bCol);
        *(float4*)(&Bs[bRow][bCol]) = bv;
        __syncthreads();

#pragma unroll
        for (int k = 0; k < 8; k++) {
            float ra[8], rb[8];
#pragma unroll
            for (int i = 0; i < 8; i++) ra[i] = As[k][ty + i];
#pragma unroll
            for (int j = 0; j < 8; j++) rb[j] = Bs[k][tx + j];
#pragma unroll
            for (int i = 0; i < 8; i++)
#pragma unroll
                for (int j = 0; j < 8; j++) acc[i][j] += ra[i] * rb[j];
        }
        __syncthreads();
    }

#pragma unroll
    for (int i = 0; i < 8; i++) {
#pragma unroll
        for (int j = 0; j < 8; j += 4) {
            float4 v;
            v.x = acc[i][j + 0] + bias[col0 + tx + j + 0];
            v.y = acc[i][j + 1] + bias[col0 + tx + j + 1];
            v.z = acc[i][j + 2] + bias[col0 + tx + j + 2];
            v.w = acc[i][j + 3] + bias[col0 + tx + j + 3];
            *(float4*)(g_xz + (size_t)(row0 + ty + i) * G4 + col0 + tx + j) = v;
        }
    }
}

// ---------------------------------------------------------------------------
// Kernel 2: one LSTM timestep.
// grid = 128 CTAs; CTA owns 8 hidden dims (d0..d0+7) across all 4 gates:
// computes z tile [32 batches x 32 cols], cols j: gate=j>>3, dd=j&7,
// global col = gate*1024 + d0 + dd.  Then gates + c/h update + residual tanh.
// ---------------------------------------------------------------------------
__device__ __forceinline__ float sigf(float v) { return 1.0f / (1.0f + expf(-v)); }

__global__ __launch_bounds__(256) void lstm_step(const float* __restrict__ U,
                                                 const float* __restrict__ x,
                                                 float* __restrict__ out,
                                                 int t) {
    __shared__ float hS[32][32];
    __shared__ float uS[32][32];
    __shared__ float zS[32][32];

    const float* __restrict__ hprev = g_h[t & 1];
    float* __restrict__ hcur        = g_h[(t + 1) & 1];

    const int tid = threadIdx.x;
    const int d0  = blockIdx.x * 8;

    const int j    = tid & 31;          // local col in z tile
    const int b4   = (tid >> 5) * 4;    // 4 batches per thread
    const int gate = j >> 3;
    const int dd   = j & 7;
    const int gcol = gate * H_ + d0 + dd;   // global column in [0,4H)

    // loader mapping (float4 per thread): h chunk and U chunk
    const int hb = tid >> 3;            // 0..31 (batch row)
    const int hk = (tid & 7) * 4;       // 0..28
    const int uk = tid >> 3;            // 0..31 (k row)
    const int uj = (tid & 7) * 4;       // 0..28 (local col quad)
    const int ugate = uj >> 3;
    const int ucol  = ugate * H_ + d0 + (uj & 7);

    float acc0 = 0.f, acc1 = 0.f, acc2 = 0.f, acc3 = 0.f;

    for (int k0 = 0; k0 < H_; k0 += 32) {
        float4 hv = *(const float4*)(hprev + hb * H_ + k0 + hk);
        *(float4*)&hS[hb][hk] = hv;
        float4 uv = *(const float4*)(U + (size_t)(k0 + uk) * G4 + ucol);
        *(float4*)&uS[uk][uj] = uv;
        __syncthreads();

#pragma unroll
        for (int kk = 0; kk < 32; kk++) {
            float u = uS[kk][j];
            acc0 += hS[b4 + 0][kk] * u;
            acc1 += hS[b4 + 1][kk] * u;
            acc2 += hS[b4 + 2][kk] * u;
            acc3 += hS[b4 + 3][kk] * u;
        }
        __syncthreads();
    }

    // add precomputed input projection, stage into zS
    zS[b4 + 0][j] = acc0 + g_xz[(size_t)((b4 + 0) * T_ + t) * G4 + gcol];
    zS[b4 + 1][j] = acc1 + g_xz[(size_t)((b4 + 1) * T_ + t) * G4 + gcol];
    zS[b4 + 2][j] = acc2 + g_xz[(size_t)((b4 + 2) * T_ + t) * G4 + gcol];
    zS[b4 + 3][j] = acc3 + g_xz[(size_t)((b4 + 3) * T_ + t) * G4 + gcol];
    __syncthreads();

    // gate phase: thread p -> (batch, dim) pair; 32*8 = 256 pairs
    const int b = tid >> 3;
    const int d = d0 + (tid & 7);

    float iv = zS[b][(tid & 7)];
    float fv = zS[b][8  + (tid & 7)];
    float gv = zS[b][16 + (tid & 7)];
    float ov = zS[b][24 + (tid & 7)];

    float ig = sigf(iv);
    float fg = sigf(fv);
    float gg = tanhf(gv);
    float og = sigf(ov);

    const int ci = b * H_ + d;
    float cn = fg * g_c[ci] + ig * gg;
    g_c[ci] = cn;
    float hn = og * tanhf(cn);
    hcur[ci] = hn;

    const size_t xi = (size_t)(b * T_ + t) * H_ + d;
    out[xi] = tanhf(hn + x[xi]);
}

// ---------------------------------------------------------------------------
extern "C" void kernel_launch(void* const* d_in, const int* in_sizes, int n_in,
                              void* d_out, int out_size) {
    const float* x    = (const float*)d_in[0];
    const float* W    = (const float*)d_in[1];
    const float* U    = (const float*)d_in[2];
    const float* bias = (const float*)d_in[3];
    float* out        = (float*)d_out;

    init_state<<<(B_ * H_ + 255) / 256, 256>>>();

    dim3 grid_gemm(G4 / 128, (B_ * T_) / 128);   // (32, 128)
    xw_gemm<<<grid_gemm, 256>>>(x, W, bias);

    for (int t = 0; t < T_; t++) {
        lstm_step<<<H_ / 8, 256>>>(U, x, out, t);
    }
}

// round 2
// speedup vs baseline: 3.1345x; 3.1345x over previous
#include <cuda_runtime.h>
#include <math.h>

#define B_   32
#define T_   512
#define H_   1024
#define G4   4096   // 4*H

#define NCTA      128    // persistent CTAs (1 per SM, all resident)
#define NTHREADS  256

// ---------------------------------------------------------------------------
// Persistent device scratch (no cudaMalloc allowed)
// ---------------------------------------------------------------------------
__device__ float g_xz[(size_t)B_ * T_ * G4];   // [B*T, 4H] input projection
__device__ float g_h[2][B_ * H_];              // double-buffered hidden state
__device__ unsigned g_bar_cnt;
__device__ volatile unsigned g_bar_gen;

// ---------------------------------------------------------------------------
// helpers
// ---------------------------------------------------------------------------
__device__ __forceinline__ unsigned f2tf32(float f) {
    unsigned u;
    asm("cvt.rna.tf32.f32 %0, %1;" : "=r"(u) : "f"(f));
    return u;
}

__device__ __forceinline__ void mma_tf32(float c[4],
                                         unsigned a0, unsigned a1, unsigned a2, unsigned a3,
                                         unsigned b0, unsigned b1) {
    asm volatile(
        "mma.sync.aligned.m16n8k8.row.col.f32.tf32.tf32.f32 "
        "{%0,%1,%2,%3}, {%4,%5,%6,%7}, {%8,%9}, {%0,%1,%2,%3};"
        : "+f"(c[0]), "+f"(c[1]), "+f"(c[2]), "+f"(c[3])
        : "r"(a0), "r"(a1), "r"(a2), "r"(a3), "r"(b0), "r"(b1));
}

__device__ __forceinline__ float sigf(float v) { return 1.0f / (1.0f + expf(-v)); }

// ---------------------------------------------------------------------------
// Kernel 0: zero h[0], reset barrier (every replay for determinism)
// ---------------------------------------------------------------------------
__global__ void init_state() {
    int i = blockIdx.x * blockDim.x + threadIdx.x;
    if (i < B_ * H_) g_h[0][i] = 0.0f;
    if (i == 0) { g_bar_cnt = 0; g_bar_gen = 0; }
}

// ---------------------------------------------------------------------------
// Kernel 1: xz = x @ W + b  via tf32 mma.  M=16384, N=4096, K=1024
// CTA tile 64x64, 8 warps in 2x4 grid, warp tile 32x16, BK=16.
// ---------------------------------------------------------------------------
#define AS_STRIDE 20   // 16 + pad, conflict-free A-frag loads
#define BS_STRIDE 72   // 64 + pad, conflict-free B-frag loads

__global__ __launch_bounds__(256) void xw_gemm(const float* __restrict__ X,
                                               const float* __restrict__ W,
                                               const float* __restrict__ bias) {
    __shared__ unsigned As[64 * AS_STRIDE];
    __shared__ unsigned Bs[16 * BS_STRIDE];

    const int tid   = threadIdx.x;
    const int lane  = tid & 31;
    const int w     = tid >> 5;
    const int g     = lane >> 2;   // groupID
    const int tig   = lane & 3;    // thread-in-group
    const int warpM = w >> 2;      // 0..1
    const int warpN = w & 3;       // 0..3

    const int row0 = blockIdx.y * 64;
    const int col0 = blockIdx.x * 64;

    // staging maps
    const int aRow = tid >> 2;            // 0..63
    const int aK   = (tid & 3) * 4;       // 0,4,8,12
    const int bK   = tid >> 4;            // 0..15
    const int bN   = (tid & 15) * 4;      // 0..60

    float acc[2][2][4];
#pragma unroll
    for (int i = 0; i < 2; i++)
#pragma unroll
        for (int j = 0; j < 2; j++)
#pragma unroll
            for (int k = 0; k < 4; k++) acc[i][j][k] = 0.0f;

    for (int k0 = 0; k0 < H_; k0 += 16) {
        float4 av = *(const float4*)(X + (size_t)(row0 + aRow) * H_ + k0 + aK);
        As[aRow * AS_STRIDE + aK + 0] = f2tf32(av.x);
        As[aRow * AS_STRIDE + aK + 1] = f2tf32(av.y);
        As[aRow * AS_STRIDE + aK + 2] = f2tf32(av.z);
        As[aRow * AS_STRIDE + aK + 3] = f2tf32(av.w);
        float4 bv = *(const float4*)(W + (size_t)(k0 + bK) * G4 + col0 + bN);
        Bs[bK * BS_STRIDE + bN + 0] = f2tf32(bv.x);
        Bs[bK * BS_STRIDE + bN + 1] = f2tf32(bv.y);
        Bs[bK * BS_STRIDE + bN + 2] = f2tf32(bv.z);
        Bs[bK * BS_STRIDE + bN + 3] = f2tf32(bv.w);
        __syncthreads();

#pragma unroll
        for (int kk = 0; kk < 16; kk += 8) {
            unsigned a[2][4];
#pragma unroll
            for (int mi = 0; mi < 2; mi++) {
                const unsigned* r0 = As + (warpM * 32 + mi * 16 + g) * AS_STRIDE;
                const unsigned* r1 = As + (warpM * 32 + mi * 16 + g + 8) * AS_STRIDE;
                a[mi][0] = r0[kk + tig];
                a[mi][1] = r1[kk + tig];
                a[mi][2] = r0[kk + tig + 4];
                a[mi][3] = r1[kk + tig + 4];
            }
#pragma unroll
            for (int ni = 0; ni < 2; ni++) {
                unsigned b0 = Bs[(kk + tig)     * BS_STRIDE + warpN * 16 + ni * 8 + g];
                unsigned b1 = Bs[(kk + tig + 4) * BS_STRIDE + warpN * 16 + ni * 8 + g];
#pragma unroll
                for (int mi = 0; mi < 2; mi++)
                    mma_tf32(acc[mi][ni], a[mi][0], a[mi][1], a[mi][2], a[mi][3], b0, b1);
            }
        }
        __syncthreads();
    }

    // epilogue: + bias, store fp32
#pragma unroll
    for (int mi = 0; mi < 2; mi++) {
#pragma unroll
        for (int ni = 0; ni < 2; ni++) {
            int row = row0 + warpM * 32 + mi * 16 + g;
            int col = col0 + warpN * 16 + ni * 8 + 2 * tig;
            float2 bvv = *(const float2*)(bias + col);
            float2 v0 = make_float2(acc[mi][ni][0] + bvv.x, acc[mi][ni][1] + bvv.y);
            float2 v1 = make_float2(acc[mi][ni][2] + bvv.x, acc[mi][ni][3] + bvv.y);
            *(float2*)(g_xz + (size_t)row * G4 + col)       = v0;
            *(float2*)(g_xz + (size_t)(row + 8) * G4 + col) = v1;
        }
    }
}

// ---------------------------------------------------------------------------
// Kernel 2: persistent LSTM recurrence.
// 128 CTAs x 256 threads. CTA cb owns 8 hidden dims d0=cb*8 across 4 gates
// (32 z-columns, col j: gate=j>>3, dim=d0+(j&7)).
// U slice (1024 x 32, tf32) resident in SMEM for the whole kernel.
// Per step: stage h (tf32) in two 512-k halves, z = h@Us via m16n8k8 mma
// (warp = (m-tile, k-split/4)), reduce k-partials in SMEM, gates + c (regs)
// + h (global, double-buffered) + residual tanh output, grid barrier.
// ---------------------------------------------------------------------------
#define US_STRIDE 36    // 32 + pad
#define HS_STRIDE 516   // 512 + pad (conflict-free A-frag loads, 16B-aligned rows)
#define US_WORDS  (1024 * US_STRIDE)
#define HS_WORDS  (32 * HS_STRIDE)
#define SMEM_BYTES ((US_WORDS + HS_WORDS) * 4)

__device__ __forceinline__ void grid_barrier() {
    __syncthreads();
    if (threadIdx.x == 0) {
        unsigned gen = g_bar_gen;
        __threadfence();
        unsigned t = atomicAdd(&g_bar_cnt, 1);
        if (t == NCTA - 1) {
            g_bar_cnt = 0;
            __threadfence();
            g_bar_gen = gen + 1;
        } else {
            while (g_bar_gen == gen) { __nanosleep(64); }
            __threadfence();
        }
    }
    __syncthreads();
}

__global__ __launch_bounds__(NTHREADS, 1) void lstm_persistent(
        const float* __restrict__ U,
        const float* __restrict__ x,
        float* __restrict__ out) {
    extern __shared__ unsigned smem[];
    unsigned* Us = smem;                 // [1024][US_STRIDE]
    unsigned* hS = smem + US_WORDS;      // [32][HS_STRIDE], aliased by redS after compute
    float*  redS = (float*)hS;           // [4][32][32]

    const int tid  = threadIdx.x;
    const int lane = tid & 31;
    const int w    = tid >> 5;
    const int g    = lane >> 2;
    const int tig  = lane & 3;
    const int mi   = w >> 2;    // m-tile (batches 0-15 / 16-31)
    const int ks   = w & 3;     // k-split quarter

    const int d0 = blockIdx.x * 8;

    // ---- preload U slice into SMEM (tf32), once ----
    // column j (0..31): gate=j>>3, dim=d0+(j&7) -> global col gate*1024+d0+(j&7)
    for (int idx = tid; idx < 1024 * 32; idx += NTHREADS) {
        int k = idx >> 5;
        int j = idx & 31;
        int gcol = (j >> 3) * H_ + d0 + (j & 7);
        Us[k * US_STRIDE + j] = f2tf32(U[(size_t)k * G4 + gcol]);
    }

    // gate-phase identity: thread owns (batch b, local dim dd) across 4 gates
    const int eb = tid >> 3;
    const int ed = tid & 7;
    float c_reg = 0.0f;

    // staging map: 16 float4 per thread per half
    // q = tid + i*256 in [0,4096): b = q>>7, kq = (q&127)
    grid_barrier();   // ensure init_state's h zeroing is visible (cheap, also syncs preload)

    for (int t = 0; t < T_; t++) {
        const float* __restrict__ hprev = g_h[t & 1];
        float* __restrict__ hcur        = g_h[(t + 1) & 1];

        float acc[4][4];
#pragma unroll
        for (int ni = 0; ni < 4; ni++)
#pragma unroll
            for (int q = 0; q < 4; q++) acc[ni][q] = 0.0f;

#pragma unroll
        for (int kh = 0; kh < 2; kh++) {
            // stage h[:, kh*512 .. +512] as tf32 into hS
#pragma unroll
            for (int i = 0; i < 16; i++) {
                int q  = tid + i * 256;
                int b  = q >> 7;
                int kq = (q & 127) * 4;
                float4 hv = __ldcg((const float4*)(hprev + b * H_ + kh * 512 + kq));
                unsigned* dst = hS + b * HS_STRIDE + kq;
                dst[0] = f2tf32(hv.x);
                dst[1] = f2tf32(hv.y);
                dst[2] = f2tf32(hv.z);
                dst[3] = f2tf32(hv.w);
            }
            __syncthreads();

            const unsigned* hrow0 = hS + (mi * 16 + g) * HS_STRIDE;
            const unsigned* hrow1 = hS + (mi * 16 + g + 8) * HS_STRIDE;
            const int kbase = ks * 128;
#pragma unroll 4
            for (int kk = kbase; kk < kbase + 128; kk += 8) {
                unsigned a0 = hrow0[kk + tig];
                unsigned a1 = hrow1[kk + tig];
                unsigned a2 = hrow0[kk + tig + 4];
                unsigned a3 = hrow1[kk + tig + 4];
                const unsigned* ub0 = Us + (size_t)(kh * 512 + kk + tig) * US_STRIDE;
                const unsigned* ub1 = Us + (size_t)(kh * 512 + kk + tig + 4) * US_STRIDE;
#pragma unroll
                for (int ni = 0; ni < 4; ni++) {
                    unsigned b0 = ub0[ni * 8 + g];
                    unsigned b1 = ub1[ni * 8 + g];
                    mma_tf32(acc[ni], a0, a1, a2, a3, b0, b1);
                }
            }
            __syncthreads();   // before hS is restaged / aliased
        }

        // ---- reduce 4 k-partials via SMEM (redS aliases hS) ----
#pragma unroll
        for (int ni = 0; ni < 4; ni++) {
            float* r0 = redS + ks * 1024 + (mi * 16 + g) * 32 + ni * 8 + 2 * tig;
            float* r1 = redS + ks * 1024 + (mi * 16 + g + 8) * 32 + ni * 8 + 2 * tig;
            r0[0] = acc[ni][0];
            r0[1] = acc[ni][1];
            r1[0] = acc[ni][2];
            r1[1] = acc[ni][3];
        }
        __syncthreads();

        // ---- gates + state update + residual tanh ----
        const float* rb = redS + eb * 32 + ed;
        float z[4];
#pragma unroll
        for (int gate = 0; gate < 4; gate++) {
            float s = rb[gate * 8] + rb[1024 + gate * 8] + rb[2048 + gate * 8] + rb[3072 + gate * 8];
            z[gate] = s + __ldg(&g_xz[((size_t)eb * T_ + t) * G4 + gate * H_ + d0 + ed]);
        }
        float ig = sigf(z[0]);
        float fg = sigf(z[1]);
        float gg = tanhf(z[2]);
        float og = sigf(z[3]);

        c_reg = fg * c_reg + ig * gg;
        float hn = og * tanhf(c_reg);
        hcur[eb * H_ + d0 + ed] = hn;

        const size_t xi = ((size_t)eb * T_ + t) * H_ + d0 + ed;
        out[xi] = tanhf(hn + __ldg(&x[xi]));

        grid_barrier();
    }
}

// ---------------------------------------------------------------------------
extern "C" void kernel_launch(void* const* d_in, const int* in_sizes, int n_in,
                              void* d_out, int out_size) {
    const float* x    = (const float*)d_in[0];
    const float* W    = (const float*)d_in[1];
    const float* U    = (const float*)d_in[2];
    const float* bias = (const float*)d_in[3];
    float* out        = (float*)d_out;

    cudaFuncSetAttribute(lstm_persistent,
                         cudaFuncAttributeMaxDynamicSharedMemorySize, SMEM_BYTES);

    init_state<<<(B_ * H_ + 255) / 256, 256>>>();

    dim3 grid_gemm(G4 / 64, (B_ * T_) / 64);   // (64, 256)
    xw_gemm<<<grid_gemm, 256>>>(x, W, bias);

    lstm_persistent<<<NCTA, NTHREADS, SMEM_BYTES>>>(U, x, out);
}